// round 14
// baseline (speedup 1.0000x reference)
#include <cuda_runtime.h>
#include <cuda_fp16.h>
#include <cstdint>

#define BATCH   65536
#define DIM     128
#define NPROTO  512
#define ODIM    8
#define MTILE   128
#define NCHUNK  64
#define NCHUNKS 8
#define NTHREADS 256

#define BTILE   16384                   // one split chunk: 64 rows x 256B
#define BBUF    (2 * BTILE)             // 32768 per buffer (2 splits)

#define SM_BIAS 0                       // 512 f32
#define SM_A    2048                    // 2 splits x 32768 (128 rows x 256B)
#define SM_B    (SM_A + 65536)          // 67584; 2 bufs
#define SM_MBAR (SM_B + 2 * BBUF)       // 133120; 2 mbarriers
#define SM_RED  SM_A
#define SMEM_TOTAL (SM_MBAR + 32)       // 133152 -> 1 CTA/SM

// g_w stored PRE-SWIZZLED: chunk-contiguous, within chunk r*128 + (d ^ ((r&7)<<3))
__device__ __align__(16) __half g_w[2][NPROTO * DIM];
__device__ float g_bias[NPROTO];

// ---------------- helpers ----------------
__device__ __forceinline__ uint32_t smem_u32(const void* p) {
    uint32_t a;
    asm("{ .reg .u64 t; cvta.to.shared.u64 t, %1; cvt.u32.u64 %0, t; }" : "=r"(a) : "l"(p));
    return a;
}
__device__ __forceinline__ void ldsm4(uint32_t* r, uint32_t a) {
    asm volatile("ldmatrix.sync.aligned.m8n8.x4.shared.b16 {%0,%1,%2,%3}, [%4];"
                 : "=r"(r[0]), "=r"(r[1]), "=r"(r[2]), "=r"(r[3]) : "r"(a));
}
__device__ __forceinline__ void mma16816(float* d, const uint32_t* a, const uint32_t* b) {
    asm volatile(
        "mma.sync.aligned.m16n8k16.row.col.f32.f16.f16.f32 "
        "{%0,%1,%2,%3}, {%4,%5,%6,%7}, {%8,%9}, {%0,%1,%2,%3};"
        : "+f"(d[0]), "+f"(d[1]), "+f"(d[2]), "+f"(d[3])
        : "r"(a[0]), "r"(a[1]), "r"(a[2]), "r"(a[3]), "r"(b[0]), "r"(b[1]));
}
__device__ __forceinline__ void mbar_init(uint32_t a, uint32_t cnt) {
    asm volatile("mbarrier.init.shared.b64 [%0], %1;" :: "r"(a), "r"(cnt) : "memory");
}
__device__ __forceinline__ void mbar_expect_tx(uint32_t a, uint32_t bytes) {
    asm volatile("mbarrier.arrive.expect_tx.shared.b64 _, [%0], %1;"
                 :: "r"(a), "r"(bytes) : "memory");
}
__device__ __forceinline__ void mbar_wait(uint32_t a, uint32_t parity) {
    asm volatile(
        "{\n\t.reg .pred P;\n\t"
        "WL%=:\n\t"
        "mbarrier.try_wait.parity.shared.b64 P, [%0], %1;\n\t"
        "@!P bra WL%=;\n\t}"
        :: "r"(a), "r"(parity) : "memory");
}
__device__ __forceinline__ void bulk_g2s(uint32_t dst, const void* src,
                                         uint32_t bytes, uint32_t mbar) {
    asm volatile(
        "cp.async.bulk.shared::cta.global.mbarrier::complete_tx::bytes [%0], [%1], %2, [%3];"
        :: "r"(dst), "l"(src), "r"(bytes), "r"(mbar) : "memory");
}

// ---------------------------------------------------------------------------
// Prep: fp16 h/m split of w = r^2*proto, stored pre-swizzled chunk-major; bias.
// ---------------------------------------------------------------------------
__global__ void prep_kernel(const float* __restrict__ protos,
                            const float* __restrict__ relevance) {
    int p = blockIdx.x;          // 512
    int d = threadIdx.x;         // 128
    float r  = relevance[d];
    float pv = protos[p * DIM + d];
    float w  = r * r * pv;

    __half h = __float2half_rn(w);
    __half m = __float2half_rn(w - __half2float(h));
    int chunk = p >> 6, rr = p & 63;
    int idx = chunk * (NCHUNK * DIM) + rr * DIM + (d ^ ((rr & 7) << 3));
    g_w[0][idx] = h;
    g_w[1][idx] = m;

    float part = w * pv;
    __shared__ float red[4];
    #pragma unroll
    for (int off = 16; off > 0; off >>= 1)
        part += __shfl_down_sync(0xffffffffu, part, off);
    if ((d & 31) == 0) red[d >> 5] = part;
    __syncthreads();
    if (d == 0) g_bias[p] = -0.5f * (red[0] + red[1] + red[2] + red[3]);
}

// ---------------------------------------------------------------------------
// Main: 256 threads (8 warps, 2/SMSP), warp tile 16x64. A in registers;
// B via cp.async.bulk + mbarrier; explicit register double-buffer of B frags.
// ---------------------------------------------------------------------------
extern __shared__ char smem[];

__global__ void __launch_bounds__(NTHREADS, 1)
grlvq_main(const float* __restrict__ x,
           const float* __restrict__ proto_out,
           float* __restrict__ out) {
    const uint32_t sb = smem_u32(smem);
    const int tid  = threadIdx.x;
    const int wid  = tid >> 5;
    const int lane = tid & 31;
    const int row0 = blockIdx.x * MTILE;
    const int wm = wid * 16;             // 8 M-warps x 16 rows

    if (tid == 0) {
        mbar_init(sb + SM_MBAR + 0, 1);
        mbar_init(sb + SM_MBAR + 8, 1);
    }
    __syncthreads();

    // issue B chunks 0,1
    if (tid == 0) {
        #pragma unroll
        for (int c = 0; c < 2; c++) {
            uint32_t mb = sb + SM_MBAR + c * 8;
            mbar_expect_tx(mb, 2 * BTILE);
            bulk_g2s(sb + SM_B + c * BBUF,
                     (const char*)g_w[0] + (size_t)c * BTILE, BTILE, mb);
            bulk_g2s(sb + SM_B + c * BBUF + BTILE,
                     (const char*)g_w[1] + (size_t)c * BTILE, BTILE, mb);
        }
    }

    for (int i = tid; i < NPROTO; i += NTHREADS)
        ((float*)(smem + SM_BIAS))[i] = g_bias[i];

    // ---- A: load x tile, split into fp16 h/m, swizzled 256B rows ----
    {
        const int r  = tid >> 1;              // 128 rows
        const int cb = (tid & 1) * 64;
        const float4* xr = (const float4*)(x + (size_t)(row0 + r) * DIM + cb);
        #pragma unroll
        for (int g = 0; g < 8; g++) {
            float4 v0 = xr[g * 2], v1 = xr[g * 2 + 1];
            float xv[8] = {v0.x, v0.y, v0.z, v0.w, v1.x, v1.y, v1.z, v1.w};
            uint32_t hh[4], mm[4];
            #pragma unroll
            for (int q = 0; q < 4; q++) {
                float a0 = xv[2 * q], a1 = xv[2 * q + 1];
                __half h0 = __float2half_rn(a0), h1 = __float2half_rn(a1);
                float r0 = a0 - __half2float(h0), r1f = a1 - __half2float(h1);
                __half m0 = __float2half_rn(r0), m1 = __float2half_rn(r1f);
                hh[q] = ((uint32_t)__half_as_ushort(h1) << 16) | __half_as_ushort(h0);
                mm[q] = ((uint32_t)__half_as_ushort(m1) << 16) | __half_as_ushort(m0);
            }
            uint32_t q0  = (uint32_t)(cb + g * 8) * 2;
            uint32_t off = (uint32_t)r * 256 + (q0 ^ (((uint32_t)r & 7) << 4));
            *(uint4*)(smem + SM_A +     0 + off) = make_uint4(hh[0], hh[1], hh[2], hh[3]);
            *(uint4*)(smem + SM_A + 32768 + off) = make_uint4(mm[0], mm[1], mm[2], mm[3]);
        }
    }
    __syncthreads();

    // ---- A fragments to registers once (16 ldsm4) ----
    uint32_t ah[8][4], am[8][4];
    {
        const uint32_t arow = (uint32_t)(wm + (lane & 15));
        const uint32_t base = sb + SM_A + arow * 256;
        #pragma unroll
        for (int kk = 0; kk < 8; kk++) {
            uint32_t q0 = (uint32_t)(kk * 32) + ((uint32_t)(lane >> 4)) * 16;
            uint32_t sw = q0 ^ ((arow & 7) << 4);
            ldsm4(ah[kk], base + sw);
            ldsm4(am[kk], base + 32768 + sw);
        }
    }

    float bestv[2] = {-3.402823466e38f, -3.402823466e38f};
    int   besti[2] = {0, 0};

    // B ldsm addressing: 4 groups of 16 protos each
    const uint32_t brow_in = (uint32_t)(((lane >> 4) & 1) * 8 + (lane & 7));
    const uint32_t b_kh    = ((uint32_t)(lane >> 3) & 1) * 16;

    // explicit double-buffered B fragments: [buf][group of 16 cols][4 regs]
    #define LOAD_BFRAGS(buf, bbase, kk)                                          \
        do {                                                                     \
            uint32_t q0 = (uint32_t)((kk) * 32) + b_kh;                          \
            _Pragma("unroll")                                                    \
            for (int nq = 0; nq < 4; nq++) {                                     \
                uint32_t brow = brow_in + nq * 16;                               \
                uint32_t addr = (bbase) + brow * 256 + (q0 ^ ((brow & 7) << 4)); \
                ldsm4(bH[buf][nq], addr);                                        \
                ldsm4(bM[buf][nq], addr + BTILE);                                \
            }                                                                    \
        } while (0)

    for (int c = 0; c < NCHUNKS; c++) {
        mbar_wait(sb + SM_MBAR + (c & 1) * 8, (c >> 1) & 1);
        const uint32_t bbase = sb + SM_B + (c & 1) * BBUF;

        float acc[8][4];                     // 8 n8 slices
        #pragma unroll
        for (int nt = 0; nt < 8; nt++)
            #pragma unroll
            for (int j = 0; j < 4; j++) acc[nt][j] = 0.0f;

        uint32_t bH[2][4][4], bM[2][4][4];
        LOAD_BFRAGS(0, bbase, 0);

        #pragma unroll
        for (int kk = 0; kk < 8; kk++) {
            const int cur = kk & 1;
            if (kk < 7) LOAD_BFRAGS((kk + 1) & 1, bbase, kk + 1);
            #pragma unroll
            for (int nq = 0; nq < 4; nq++) {
                #pragma unroll
                for (int n2 = 0; n2 < 2; n2++) {
                    float* a4 = acc[nq * 2 + n2];
                    mma16816(a4, ah[kk], &bH[cur][nq][n2 * 2]);   // h*H
                    mma16816(a4, ah[kk], &bM[cur][nq][n2 * 2]);   // h*M
                    mma16816(a4, am[kk], &bH[cur][nq][n2 * 2]);   // m*H
                }
            }
        }

        // ---- epilogue: bias + running argmax (ascending cols keep first idx) ----
        const float* bias_s = (const float*)(smem + SM_BIAS);
        const int cb0 = c * NCHUNK + (lane & 3) * 2;
        #pragma unroll
        for (int nt = 0; nt < 8; nt++) {
            const int col = cb0 + nt * 8;
            float b0 = bias_s[col], b1 = bias_s[col + 1];
            float v0 = acc[nt][0] + b0;     // row r
            float v1 = acc[nt][1] + b1;
            float v2 = acc[nt][2] + b0;     // row r+8
            float v3 = acc[nt][3] + b1;
            if (v0 > bestv[0]) { bestv[0] = v0; besti[0] = col; }
            if (v1 > bestv[0]) { bestv[0] = v1; besti[0] = col + 1; }
            if (v2 > bestv[1]) { bestv[1] = v2; besti[1] = col; }
            if (v3 > bestv[1]) { bestv[1] = v3; besti[1] = col + 1; }
        }

        __syncthreads();                     // all warps done reading slot c&1
        if (c + 2 < NCHUNKS && tid == 0) {
            const int cn = c + 2;
            uint32_t mb = sb + SM_MBAR + (cn & 1) * 8;
            mbar_expect_tx(mb, 2 * BTILE);
            bulk_g2s(sb + SM_B + (cn & 1) * BBUF,
                     (const char*)g_w[0] + (size_t)cn * BTILE, BTILE, mb);
            bulk_g2s(sb + SM_B + (cn & 1) * BBUF + BTILE,
                     (const char*)g_w[1] + (size_t)cn * BTILE, BTILE, mb);
        }
    }

    // ---- cross-thread reduction: 4 candidates per row ----
    float* redv = (float*)(smem + SM_RED);
    int*   redi = (int*)(smem + SM_RED + 2048);
    const int slot = lane & 3;               // 0..3
    {
        int r0 = wm + (lane >> 2);
        redv[r0 * 4 + slot] = bestv[0];
        redi[r0 * 4 + slot] = besti[0];
        redv[(r0 + 8) * 4 + slot] = bestv[1];
        redi[(r0 + 8) * 4 + slot] = besti[1];
    }
    __syncthreads();

    if (tid < MTILE) {
        float bv = redv[tid * 4];
        int   bi = redi[tid * 4];
        #pragma unroll
        for (int j = 1; j < 4; j++) {
            float v  = redv[tid * 4 + j];
            int   ix = redi[tid * 4 + j];
            if (v > bv || (v == bv && ix < bi)) { bv = v; bi = ix; }
        }
        const float4* po = (const float4*)proto_out;
        float4* o = (float4*)(out + (size_t)(row0 + tid) * ODIM);
        o[0] = po[bi * 2];
        o[1] = po[bi * 2 + 1];
    }
}

// ---------------------------------------------------------------------------
extern "C" void kernel_launch(void* const* d_in, const int* in_sizes, int n_in,
                              void* d_out, int out_size) {
    const float* x         = (const float*)d_in[0];  // [65536,128]
    const float* protos    = (const float*)d_in[1];  // [512,128]
    const float* proto_out = (const float*)d_in[2];  // [512,8]
    const float* relevance = (const float*)d_in[3];  // [128]
    float* out = (float*)d_out;                      // [65536,8]

    prep_kernel<<<NPROTO, DIM>>>(protos, relevance);

    cudaFuncSetAttribute(grlvq_main,
                         cudaFuncAttributeMaxDynamicSharedMemorySize, SMEM_TOTAL);
    grlvq_main<<<BATCH / MTILE, NTHREADS, SMEM_TOTAL>>>(x, proto_out, out);
}